// round 14
// baseline (speedup 1.0000x reference)
#include <cuda_runtime.h>
#include <cstdint>

// One row per warp, 8 warps (256 threads) per block.
#define RPB 8
#define MAX_PARTIALS 32768
__device__ float g_partials[MAX_PARTIALS];
__device__ unsigned int g_count = 0;

// __expf = FMUL + MUFU.EX2: 2 issue slots, ~2^-22 rel err. MUFU pipe is
// otherwise idle here and its chip throughput (~28us for 131M elems) hides
// fully under the ~75us memory time.

__global__ void __launch_bounds__(256)
mae_kernel(const float* __restrict__ logits,
           const int* __restrict__ targets,     // int32 (JAX demotes int64)
           float* __restrict__ out,
           int B, int C, float invB, int nblocks)
{
    const int lane = threadIdx.x & 31;
    const int warp = threadIdx.x >> 5;
    const int row  = blockIdx.x * RPB + warp;

    __shared__ float s_p[RPB];
    __shared__ bool  s_last;

    float p_t = 0.0f;
    if (row < B) {
        const size_t base = (size_t)row * (size_t)C;
        const float4* rp = reinterpret_cast<const float4*>(logits + base);
        const int C4 = C >> 2;

        // Front-batch 8 independent 16B loads per thread (MLP=8), covering
        // 8*32*4 = 1024 >= C elements. OOB slots -> -80 (exp ~ 0).
        float4 v[8];
        #pragma unroll
        for (int k = 0; k < 8; k++) {
            int j = lane + (k << 5);
            if (j < C4) v[k] = rp[j];
            else        v[k] = make_float4(-80.0f, -80.0f, -80.0f, -80.0f);
        }

        // Target gather overlaps the exp evaluation below.
        float ext = 0.0f;
        if (lane == 0) {
            int t = targets[row];
            t = (t < 0) ? 0 : ((t >= C) ? C - 1 : t);
            ext = __expf(__ldg(logits + base + (size_t)t));
        }

        float a0 = 0.0f, a1 = 0.0f, a2 = 0.0f, a3 = 0.0f;
        #pragma unroll
        for (int k = 0; k < 8; k++) {
            a0 += __expf(v[k].x);
            a1 += __expf(v[k].y);
            a2 += __expf(v[k].z);
            a3 += __expf(v[k].w);
        }
        // Generic tails (unused for C=1000, kept for safety).
        for (int c = (C4 << 2) + lane; c < C; c += 32)
            a0 += __expf(logits[base + c]);
        for (int j = lane + 256; j < C4; j += 32) {
            float4 w = rp[j];
            a0 += __expf(w.x); a1 += __expf(w.y);
            a2 += __expf(w.z); a3 += __expf(w.w);
        }

        float acc = (a0 + a1) + (a2 + a3);
        #pragma unroll
        for (int o = 16; o; o >>= 1)
            acc += __shfl_xor_sync(0xFFFFFFFFu, acc, o);

        if (lane == 0) p_t = ext / acc;
    }

    // ---- block reduction ----
    if (lane == 0) s_p[warp] = p_t;
    __syncthreads();

    if (threadIdx.x == 0) {
        float bsum = 0.0f;
        #pragma unroll
        for (int w = 0; w < RPB; w++) bsum += s_p[w];
        g_partials[blockIdx.x] = bsum;
        __threadfence();
        unsigned int t = atomicAdd(&g_count, 1u);
        s_last = (t == (unsigned)nblocks - 1u);
    }
    __syncthreads();

    // ---- last arriving block: deterministic-order final reduction ----
    if (s_last) {
        __shared__ float sh[8];
        float s = 0.0f;
        for (int i = threadIdx.x; i < nblocks; i += 256)
            s += __ldcg(&g_partials[i]);

        #pragma unroll
        for (int o = 16; o; o >>= 1)
            s += __shfl_xor_sync(0xFFFFFFFFu, s, o);
        if (lane == 0) sh[warp] = s;
        __syncthreads();

        if (threadIdx.x < 32) {
            float v2 = (threadIdx.x < 8) ? sh[threadIdx.x] : 0.0f;
            #pragma unroll
            for (int o = 16; o; o >>= 1)
                v2 += __shfl_xor_sync(0xFFFFFFFFu, v2, o);
            if (threadIdx.x == 0) {
                out[0] = 2.0f - 2.0f * v2 * invB;
                g_count = 0;   // reset for next graph replay
            }
        }
    }
}

extern "C" void kernel_launch(void* const* d_in, const int* in_sizes, int n_in,
                              void* d_out, int out_size)
{
    const float* logits  = (const float*)d_in[0];
    const int*   targets = (const int*)d_in[1];
    float*       out     = (float*)d_out;

    const int B = in_sizes[1];
    const int C = in_sizes[0] / B;

    int grid = (B + RPB - 1) / RPB;        // 16384 for B=131072
    if (grid > MAX_PARTIALS) grid = MAX_PARTIALS;

    mae_kernel<<<grid, 256>>>(logits, targets, out, B, C, 1.0f / (float)B, grid);
}